// round 4
// baseline (speedup 1.0000x reference)
#include <cuda_runtime.h>
#include <math.h>

#define Bsz  4096
#define Tt   512
#define INP  25
#define Hh   50
#define Gg   200
#define ROWS 28
#define NTH  704
#define GRID 147
#define WST  204        // wh_s row stride (floats)

// ---- Device scratch (module-allocated, zero-init bss; no runtime alloc) ----
__device__ float g_precomp[(size_t)Tt * Bsz * Gg];   // [T][B][200] = x@wi + b
__device__ float g_wib[INP * Gg + Gg];               // sampled wi (5000) + bias (200)

__device__ __forceinline__ float sigf(float v) {
    return 1.0f / (1.0f + __expf(-v));
}
__device__ __forceinline__ float tanh_fast(float v) {
    return fmaf(2.0f, 1.0f / (1.0f + __expf(-2.0f * v)), -1.0f);
}

#define FMA16(w, hv)                                                       \
    acc[0][0] = fmaf(w.x, hv.x, acc[0][0]);                                \
    acc[0][1] = fmaf(w.x, hv.y, acc[0][1]);                                \
    acc[0][2] = fmaf(w.x, hv.z, acc[0][2]);                                \
    acc[0][3] = fmaf(w.x, hv.w, acc[0][3]);                                \
    acc[1][0] = fmaf(w.y, hv.x, acc[1][0]);                                \
    acc[1][1] = fmaf(w.y, hv.y, acc[1][1]);                                \
    acc[1][2] = fmaf(w.y, hv.z, acc[1][2]);                                \
    acc[1][3] = fmaf(w.y, hv.w, acc[1][3]);                                \
    acc[2][0] = fmaf(w.z, hv.x, acc[2][0]);                                \
    acc[2][1] = fmaf(w.z, hv.y, acc[2][1]);                                \
    acc[2][2] = fmaf(w.z, hv.z, acc[2][2]);                                \
    acc[2][3] = fmaf(w.z, hv.w, acc[2][3]);                                \
    acc[3][0] = fmaf(w.w, hv.x, acc[3][0]);                                \
    acc[3][1] = fmaf(w.w, hv.y, acc[3][1]);                                \
    acc[3][2] = fmaf(w.w, hv.z, acc[3][2]);                                \
    acc[3][3] = fmaf(w.w, hv.w, acc[3][3]);

// ---- Kernel 0: sample wi and bias once ----
__global__ void sample_wi_kernel(const float* __restrict__ wi_mu, const float* __restrict__ wi_rho,
                                 const float* __restrict__ eps_wi,
                                 const float* __restrict__ b_mu,  const float* __restrict__ b_rho,
                                 const float* __restrict__ eps_b)
{
    int i = blockIdx.x * blockDim.x + threadIdx.x;
    if (i < INP * Gg) {
        g_wib[i] = fmaf(log1pf(__expf(wi_rho[i])), eps_wi[i], wi_mu[i]);
    } else if (i < INP * Gg + Gg) {
        int j = i - INP * Gg;
        g_wib[i] = fmaf(log1pf(__expf(b_rho[j])), eps_b[j], b_mu[j]);
    }
}

// ---- Kernel 1: precomp[t][b][:] = x[b][t][:] @ wi + bias ----
#define GT  400          // threads: 25 col-groups x 16 row-groups
#define BR  64           // batch rows per CTA
__global__ void __launch_bounds__(GT)
input_gemm_kernel(const float* __restrict__ x)
{
    __shared__ float wi_s[INP * WST];     // stride 204
    __shared__ float bias_s[Gg];
    __shared__ float x_s[INP * 68];       // [k][r], stride 68

    const int tid = threadIdx.x;
    const int t  = blockIdx.x >> 6;       // / 64
    const int b0 = (blockIdx.x & 63) * BR;

    for (int i = tid; i < INP * Gg; i += GT) {
        int k = i / Gg, j = i - k * Gg;
        wi_s[k * WST + j] = g_wib[i];
    }
    for (int i = tid; i < Gg; i += GT) bias_s[i] = g_wib[INP * Gg + i];
    for (int i = tid; i < BR * INP; i += GT) {
        int r = i / INP, k = i - r * INP;
        x_s[k * 68 + r] = x[((size_t)(b0 + r) * Tt + t) * INP + k];
    }
    __syncthreads();

    const int cg = tid % 25, rg = tid / 25;   // 25 x 16
    const int j0 = cg * 8, r0 = rg * 4;

    float acc[8][4];
    #pragma unroll
    for (int u = 0; u < 8; u++) {
        float bv = bias_s[j0 + u];
        #pragma unroll
        for (int v = 0; v < 4; v++) acc[u][v] = bv;
    }
    #pragma unroll 5
    for (int k = 0; k < INP; k++) {
        const float* wk = wi_s + k * WST + j0;
        float4 wa = *(const float4*)(wk);
        float4 wb = *(const float4*)(wk + 4);
        float4 xv = *(const float4*)(x_s + k * 68 + r0);
        float wr[8] = {wa.x, wa.y, wa.z, wa.w, wb.x, wb.y, wb.z, wb.w};
        float xr[4] = {xv.x, xv.y, xv.z, xv.w};
        #pragma unroll
        for (int u = 0; u < 8; u++)
            #pragma unroll
            for (int v = 0; v < 4; v++)
                acc[u][v] = fmaf(wr[u], xr[v], acc[u][v]);
    }
    #pragma unroll
    for (int v = 0; v < 4; v++) {
        size_t orow = (size_t)t * Bsz + (size_t)(b0 + r0 + v);
        *(float4*)(g_precomp + orow * Gg + j0) =
            make_float4(acc[0][v], acc[1][v], acc[2][v], acc[3][v]);
        *(float4*)(g_precomp + orow * Gg + j0 + 4) =
            make_float4(acc[4][v], acc[5][v], acc[6][v], acc[7][v]);
    }
}

// ---- Kernel 2: serial scan, gates = precomp[t] + h @ wh ----
__global__ void __launch_bounds__(NTH, 1)
scan_kernel(const float* __restrict__ wh_mu, const float* __restrict__ wh_rho,
            const float* __restrict__ eps_wh,
            const float* __restrict__ lin_w, const float* __restrict__ lin_b,
            float* __restrict__ out)
{
    extern __shared__ float sm[];
    float* wh_s    = sm;                    // [50][WST]  10200
    float* h_s     = wh_s + Hh * WST;       // [50][28]    1400
    float* c_s     = h_s + Hh * ROWS;       // [50][28]    1400
    float* gates_s = c_s + Hh * ROWS;       // [200][28]   5600

    const int tid  = threadIdx.x;
    const long row0 = (long)blockIdx.x * ROWS;

    // sample wh into SMEM (padded stride)
    for (int i = tid; i < Hh * Gg; i += NTH) {
        int k = i / Gg, j = i - k * Gg;
        wh_s[k * WST + j] = fmaf(log1pf(__expf(wh_rho[i])), eps_wh[i], wh_mu[i]);
    }
    for (int i = tid; i < Hh * ROWS; i += NTH) { h_s[i] = 0.0f; c_s[i] = 0.0f; }
    __syncthreads();

    // pair split-K task map (proven R2 structure)
    const bool store_ok = (tid < 700);
    const int  tile = store_ok ? (tid >> 1) : 349;
    const int  kh   = tid & 1;
    const int  j0   = (tile % 50) * 4;
    const int  rr0  = (tile / 50) * 4;
    const int  kbeg = kh ? 25 : 0;

    // precomp rows owned by this lane: v-columns {2kh, 2kh+1}
    const long grA = row0 + rr0 + 2 * kh;
    const long grB = grA + 1;
    const bool okA = (grA < Bsz), okB = (grB < Bsz);
    const float4* __restrict__ pcp = (const float4*)g_precomp;

    float4 pA = make_float4(0.f,0.f,0.f,0.f), pB = pA;
    if (okA) pA = pcp[((size_t)grA * Gg + j0) >> 2];          // t = 0
    if (okB) pB = pcp[((size_t)grB * Gg + j0) >> 2];

    const float* wp = wh_s + j0;
    const float* vp = h_s + rr0;

    for (int t = 0; t < Tt; ++t) {
        // prefetch precomp for t+1 (latency hidden under gate compute)
        float4 nA = make_float4(0.f,0.f,0.f,0.f), nB = nA;
        if (t + 1 < Tt) {
            size_t base = (size_t)(t + 1) * Bsz;
            if (okA) nA = pcp[((base + grA) * Gg + j0) >> 2];
            if (okB) nB = pcp[((base + grB) * Gg + j0) >> 2];
        }

        // ---- gate compute: acc init from precomp on this lane's v-columns ----
        float acc[4][4];
        #pragma unroll
        for (int u = 0; u < 4; u++)
            #pragma unroll
            for (int v = 0; v < 4; v++) acc[u][v] = 0.0f;
        {
            const int vA = 2 * kh;
            acc[0][vA] = pA.x; acc[1][vA] = pA.y; acc[2][vA] = pA.z; acc[3][vA] = pA.w;
            acc[0][vA+1] = pB.x; acc[1][vA+1] = pB.y; acc[2][vA+1] = pB.z; acc[3][vA+1] = pB.w;
        }
        #pragma unroll 5
        for (int k = kbeg; k < kbeg + 25; k++) {
            float4 w  = *(const float4*)(wp + k * WST);
            float4 hv = *(const float4*)(vp + k * ROWS);
            FMA16(w, hv)
        }
        // pair reduction
        #pragma unroll
        for (int u = 0; u < 4; u++)
            #pragma unroll
            for (int v = 0; v < 4; v++)
                acc[u][v] += __shfl_xor_sync(0xffffffffu, acc[u][v], 1);
        // each parity stores 2 of the 4 gate rows
        if (store_ok) {
            const int u0 = 2 * kh;
            *(float4*)(gates_s + (j0 + u0) * ROWS + rr0) =
                make_float4(acc[u0][0], acc[u0][1], acc[u0][2], acc[u0][3]);
            *(float4*)(gates_s + (j0 + u0 + 1) * ROWS + rr0) =
                make_float4(acc[u0+1][0], acc[u0+1][1], acc[u0+1][2], acc[u0+1][3]);
        }
        __syncthreads();

        // ---- epilogue ----
        for (int i = tid; i < Hh * ROWS; i += NTH) {
            float gi = gates_s[i];
            float gf = gates_s[Hh * ROWS + i];
            float gg = gates_s[2 * Hh * ROWS + i];
            float go = gates_s[3 * Hh * ROWS + i];
            float iv = sigf(gi);
            float fv = sigf(gf);
            float gv = tanh_fast(gg);
            float ov = sigf(go);
            float c  = fmaf(fv, c_s[i], iv * gv);
            c_s[i] = c;
            h_s[i] = ov * tanh_fast(c);
        }
        __syncthreads();

        pA = nA; pB = nB;
    }

    // ---- head ----
    for (int r = tid; r < ROWS; r += NTH) {
        if (row0 + r < Bsz) {
            float s = lin_b[0];
            #pragma unroll
            for (int m = 0; m < Hh; m++)
                s = fmaf(h_s[m * ROWS + r], lin_w[m], s);
            out[row0 + r] = s;
        }
    }
}

extern "C" void kernel_launch(void* const* d_in, const int* in_sizes, int n_in,
                              void* d_out, int out_size)
{
    const float* x      = (const float*)d_in[0];
    const float* wi_mu  = (const float*)d_in[1];
    const float* wi_rho = (const float*)d_in[2];
    const float* wh_mu  = (const float*)d_in[3];
    const float* wh_rho = (const float*)d_in[4];
    const float* b_mu   = (const float*)d_in[5];
    const float* b_rho  = (const float*)d_in[6];
    const float* lin_w  = (const float*)d_in[7];
    const float* lin_b  = (const float*)d_in[8];
    const float* eps_wi = (const float*)d_in[9];
    const float* eps_wh = (const float*)d_in[10];
    const float* eps_b  = (const float*)d_in[11];

    sample_wi_kernel<<<21, 256>>>(wi_mu, wi_rho, eps_wi, b_mu, b_rho, eps_b);
    input_gemm_kernel<<<Tt * 64, GT>>>(x);

    const size_t smem_bytes =
        (size_t)(Hh * WST + 2 * Hh * ROWS + Gg * ROWS) * sizeof(float);  // 74400 B
    cudaFuncSetAttribute(scan_kernel,
                         cudaFuncAttributeMaxDynamicSharedMemorySize,
                         (int)smem_bytes);
    scan_kernel<<<GRID, NTH, smem_bytes>>>(wh_mu, wh_rho, eps_wh,
                                           lin_w, lin_b, (float*)d_out);
}

// round 5
// speedup vs baseline: 2.0421x; 2.0421x over previous
#include <cuda_runtime.h>
#include <math.h>

#define Bsz  4096
#define Tt   512
#define INP  25
#define Hh   50
#define Gg   200
#define KTOT 75
#define KSPL 37
#define ROWS 28
#define NTH  704
#define GRID 147

typedef unsigned long long u64;

__device__ __forceinline__ float sigf(float v) {
    return 1.0f / (1.0f + __expf(-v));
}
__device__ __forceinline__ float tanh_fast(float v) {
    return fmaf(2.0f, 1.0f / (1.0f + __expf(-2.0f * v)), -1.0f);
}

__device__ __forceinline__ u64 pack2(float lo, float hi) {
    u64 d; asm("mov.b64 %0, {%1, %2};" : "=l"(d) : "f"(lo), "f"(hi)); return d;
}
__device__ __forceinline__ void unpack2(u64 d, float& lo, float& hi) {
    asm("mov.b64 {%0, %1}, %2;" : "=f"(lo), "=f"(hi) : "l"(d));
}
__device__ __forceinline__ u64 fma2(u64 a, u64 b, u64 c) {
    u64 d; asm("fma.rn.f32x2 %0, %1, %2, %3;" : "=l"(d) : "l"(a), "l"(b), "l"(c)); return d;
}
__device__ __forceinline__ u64 add2(u64 a, u64 b) {
    u64 d; asm("add.rn.f32x2 %0, %1, %2;" : "=l"(d) : "l"(a), "l"(b)); return d;
}
__device__ __forceinline__ u64 shfl_xor64(u64 v, int m) {
    float lo, hi; unpack2(v, lo, hi);
    lo = __shfl_xor_sync(0xffffffffu, lo, m);
    hi = __shfl_xor_sync(0xffffffffu, hi, m);
    return pack2(lo, hi);
}

__global__ void __launch_bounds__(NTH, 1)
bayes_lstm_kernel(const float* __restrict__ x,
                  const float* __restrict__ wi_mu, const float* __restrict__ wi_rho,
                  const float* __restrict__ wh_mu, const float* __restrict__ wh_rho,
                  const float* __restrict__ b_mu,  const float* __restrict__ b_rho,
                  const float* __restrict__ lin_w, const float* __restrict__ lin_b,
                  const float* __restrict__ eps_wi, const float* __restrict__ eps_wh,
                  const float* __restrict__ eps_b,
                  float* __restrict__ out)
{
    extern __shared__ float sm[];
    float* w_s     = sm;                       // [KTOT][Gg]   15000
    float* bias_s  = w_s + KTOT * Gg;          // [Gg]           200
    float* xh_s    = bias_s + Gg;              // [KTOT][ROWS]  2100 (x rows 0..24, h rows 25..74)
    float* c_s     = xh_s + KTOT * ROWS;       // [Hh][ROWS]    1400
    float* gates_s = c_s + Hh * ROWS;          // [Gg][ROWS]    5600

    const int tid  = threadIdx.x;
    const long row0 = (long)blockIdx.x * ROWS;

    // ---- One-time: sample fused weights w = mu + softplus(rho) * eps ----
    for (int i = tid; i < KTOT * Gg; i += NTH) {
        float mu, rho, ep;
        if (i < INP * Gg) { mu = wi_mu[i]; rho = wi_rho[i]; ep = eps_wi[i]; }
        else { int j = i - INP * Gg; mu = wh_mu[j]; rho = wh_rho[j]; ep = eps_wh[j]; }
        w_s[i] = fmaf(log1pf(__expf(rho)), ep, mu);
    }
    for (int i = tid; i < Gg; i += NTH)
        bias_s[i] = fmaf(log1pf(__expf(b_rho[i])), eps_b[i], b_mu[i]);
    for (int i = tid; i < Hh * ROWS; i += NTH) {
        xh_s[INP * ROWS + i] = 0.0f;
        c_s[i] = 0.0f;
    }
    {
        const int r = tid / INP, k = tid % INP;
        if (tid < INP * ROWS) {
            float v = 0.0f;
            if (row0 + r < Bsz) v = x[(size_t)(row0 + r) * (Tt * INP) + k];
            xh_s[k * ROWS + r] = v;
        }
    }
    __syncthreads();

    // Split-K task map: pair of lane-adjacent threads per 4x4 tile
    const bool store_ok = (tid < 700);
    const int  tile = store_ok ? (tid >> 1) : 349;
    const int  kh   = tid & 1;
    const int  j0   = (tile % 50) * 4;
    const int  rr0  = (tile / 50) * 4;
    const int  kbeg = kh ? KSPL : 0;
    const int  kend = kh ? KTOT : KSPL;

    // packed bias (injected on kh==0 lanes, flows through the pair reduction)
    const u64 bias01 = (kh == 0) ? pack2(bias_s[j0],     bias_s[j0 + 1]) : 0ull;
    const u64 bias23 = (kh == 0) ? pack2(bias_s[j0 + 2], bias_s[j0 + 3]) : 0ull;

    // x prefetch map
    const int  pr = tid / INP, pk = tid % INP;
    const bool pf_ok = (tid < INP * ROWS) && (row0 + pr < Bsz);
    const size_t pf_base = pf_ok ? ((size_t)(row0 + pr) * (Tt * INP) + pk) : 0;

    const float* wp = w_s + j0;
    const float* vp = xh_s + rr0;

    for (int t = 0; t < Tt; ++t) {
        float pf = 0.0f;
        if (pf_ok && t + 1 < Tt) pf = x[pf_base + (size_t)(t + 1) * INP];

        // ---- Gate compute (packed f32x2, j-pairs in the 64-bit lanes) ----
        // acc01[v]: gates (j0, j0+1) for row rr0+v ; acc23[v]: gates (j0+2, j0+3)
        u64 acc01[4], acc23[4];
        #pragma unroll
        for (int v = 0; v < 4; v++) { acc01[v] = bias01; acc23[v] = bias23; }

        #pragma unroll 4
        for (int k = kbeg; k < kend; k++) {
            float4 w  = *(const float4*)(wp + k * Gg);
            float4 hv = *(const float4*)(vp + k * ROWS);
            u64 w01 = pack2(w.x, w.y);
            u64 w23 = pack2(w.z, w.w);
            u64 h0  = pack2(hv.x, hv.x);
            u64 h1  = pack2(hv.y, hv.y);
            u64 h2  = pack2(hv.z, hv.z);
            u64 h3  = pack2(hv.w, hv.w);
            acc01[0] = fma2(w01, h0, acc01[0]);
            acc01[1] = fma2(w01, h1, acc01[1]);
            acc01[2] = fma2(w01, h2, acc01[2]);
            acc01[3] = fma2(w01, h3, acc01[3]);
            acc23[0] = fma2(w23, h0, acc23[0]);
            acc23[1] = fma2(w23, h1, acc23[1]);
            acc23[2] = fma2(w23, h2, acc23[2]);
            acc23[3] = fma2(w23, h3, acc23[3]);
        }

        // ---- Pair split-K reduction (lanes differ in bit 0) ----
        #pragma unroll
        for (int v = 0; v < 4; v++) {
            acc01[v] = add2(acc01[v], shfl_xor64(acc01[v], 1));
            acc23[v] = add2(acc23[v], shfl_xor64(acc23[v], 1));
        }

        // Each parity stores 2 of the 4 gate rows of the tile
        if (store_ok) {
            float a0, a1, b0v, b1, c0v, c1, d0, d1;
            if (kh == 0) {
                unpack2(acc01[0], a0, a1); unpack2(acc01[1], b0v, b1);
                unpack2(acc01[2], c0v, c1); unpack2(acc01[3], d0, d1);
                *(float4*)(gates_s + j0 * ROWS + rr0)       = make_float4(a0, b0v, c0v, d0);
                *(float4*)(gates_s + (j0 + 1) * ROWS + rr0) = make_float4(a1, b1, c1, d1);
            } else {
                unpack2(acc23[0], a0, a1); unpack2(acc23[1], b0v, b1);
                unpack2(acc23[2], c0v, c1); unpack2(acc23[3], d0, d1);
                *(float4*)(gates_s + (j0 + 2) * ROWS + rr0) = make_float4(a0, b0v, c0v, d0);
                *(float4*)(gates_s + (j0 + 3) * ROWS + rr0) = make_float4(a1, b1, c1, d1);
            }
        }
        __syncthreads();   // gates ready; all xh reads of step t complete

        // Commit prefetched x(t+1)
        if (pf_ok && t + 1 < Tt) xh_s[pk * ROWS + pr] = pf;

        // ---- Epilogue ----
        for (int i = tid; i < Hh * ROWS; i += NTH) {
            float gi = gates_s[i];
            float gf = gates_s[Hh * ROWS + i];
            float gg = gates_s[2 * Hh * ROWS + i];
            float go = gates_s[3 * Hh * ROWS + i];
            float iv = sigf(gi);
            float fv = sigf(gf);
            float gv = tanh_fast(gg);
            float ov = sigf(go);
            float c  = fmaf(fv, c_s[i], iv * gv);
            c_s[i] = c;
            xh_s[INP * ROWS + i] = ov * tanh_fast(c);
        }
        __syncthreads();   // h, c, x(t+1) ready
    }

    // ---- Head ----
    for (int r = tid; r < ROWS; r += NTH) {
        if (row0 + r < Bsz) {
            float s = lin_b[0];
            #pragma unroll
            for (int m = 0; m < Hh; m++)
                s = fmaf(xh_s[(INP + m) * ROWS + r], lin_w[m], s);
            out[row0 + r] = s;
        }
    }
}

extern "C" void kernel_launch(void* const* d_in, const int* in_sizes, int n_in,
                              void* d_out, int out_size)
{
    const size_t smem_bytes =
        (size_t)(KTOT * Gg + Gg + KTOT * ROWS + Hh * ROWS + Gg * ROWS + 16)
        * sizeof(float);   // ~97.3 KB
    cudaFuncSetAttribute(bayes_lstm_kernel,
                         cudaFuncAttributeMaxDynamicSharedMemorySize,
                         (int)smem_bytes);
    bayes_lstm_kernel<<<GRID, NTH, smem_bytes>>>(
        (const float*)d_in[0],  (const float*)d_in[1],  (const float*)d_in[2],
        (const float*)d_in[3],  (const float*)d_in[4],  (const float*)d_in[5],
        (const float*)d_in[6],  (const float*)d_in[7],  (const float*)d_in[8],
        (const float*)d_in[9],  (const float*)d_in[10], (const float*)d_in[11],
        (float*)d_out);
}